// round 11
// baseline (speedup 1.0000x reference)
#include <cuda_runtime.h>
#include <math.h>

// Fused CNN + analytic quantum circuit. One CTA per TWO images, 320 threads.
// conv2 uses Blackwell fma.rn.f32x2 with ALL pairs pre-packed in shared memory
// (aligned + shifted activation copies, duplicated weights) -> zero runtime
// packing MOVs, half the fma-pipe instructions of the scalar version.
//
// Quantum part collapses analytically:
//   P_i(1) = (1 + sin f_i)/2
//   <Z_j>  = - sum_{b in {0,1}^4} prod_i P_i(b_i) * sin( sum_{i: b_i=1} w[i][j] )
//   out_j  = sigmoid(10 * <Z_j>)

typedef unsigned long long u64;

#define PACK2(d, lo, hi) \
    asm("mov.b64 %0, {%1, %2};" : "=l"(d) : "r"(__float_as_uint(lo)), "r"(__float_as_uint(hi)))
#define UNPACK2(lo, hi, s) do { unsigned _ulo, _uhi;                               \
    asm("mov.b64 {%0, %1}, %2;" : "=r"(_ulo), "=r"(_uhi) : "l"(s));                \
    lo = __uint_as_float(_ulo); hi = __uint_as_float(_uhi); } while (0)
#define FMA2(d, a, b) \
    asm("fma.rn.f32x2 %0, %1, %2, %0;" : "+l"(d) : "l"(a), "l"(b))

// dynamic shared-memory layout (floats)
#define OFF_IMG   0        // [1600] phase A: 2 images [2*784]; phase B: s_p2 [2][800]
#define OFF_P1    1600     // [2][16][12][12] pooled conv1, aligned rows (48B stride)
#define OFF_P1S   6208     // [2][16][12][12] same values shifted left by 1
#define OFF_W2D   10816    // u64[4608]: conv2 weights HWIO, each duplicated (w,w)
#define OFF_W1    20032    // [144]
#define OFF_B1    20176    // [16]
#define OFF_B2    20192    // [32]
#define OFF_FEAT  20224    // [8]
#define SM_FLOATS 20232
#define SM_BYTES  (SM_FLOATS * 4)

__global__ __launch_bounds__(320, 2)
void hybrid_kernel(const float* __restrict__ x,
                   const float* __restrict__ w1g, const float* __restrict__ b1g,
                   const float* __restrict__ w2g, const float* __restrict__ b2g,
                   const float* __restrict__ dwg, const float* __restrict__ dbg,
                   const float* __restrict__ qwg,
                   float* __restrict__ out, int B)
{
    extern __shared__ __align__(16) float sm[];
    float* s_img  = sm + OFF_IMG;     // phase A
    float* s_p2   = sm + OFF_IMG;     // phase B (images dead after conv1)
    float* s_p1   = sm + OFF_P1;
    float* s_p1s  = sm + OFF_P1S;
    u64*   s_w2d  = (u64*)(sm + OFF_W2D);
    float* s_w1   = sm + OFF_W1;
    float* s_b1   = sm + OFF_B1;
    float* s_b2   = sm + OFF_B2;
    float* s_feat = sm + OFF_FEAT;

    const int tid  = threadIdx.x;
    const int img0 = blockIdx.x * 2;
    const bool has2 = (img0 + 1) < B;
    const int nimg = has2 ? 2 : 1;

    // ---------------- load phase ----------------
    {
        const float* xin = x + img0 * 784;
        const int cnt = nimg * 784;
        for (int i = tid; i < cnt; i += 320) s_img[i] = xin[i];
    }
    // conv2 weights: duplicate each scalar into a (w,w) u64 pair, HWIO order
    for (int i = tid; i < 4608; i += 320) {
        const float v = w2g[i];
        u64 d; PACK2(d, v, v);
        s_w2d[i] = d;
    }
    for (int i = tid; i < 144; i += 320) s_w1[i] = w1g[i];
    if (tid < 16) s_b1[tid] = b1g[tid];
    if (tid < 32) s_b2[tid] = b2g[tid];
    if (tid < 8)  s_feat[tid] = dbg[tid & 3];
    __syncthreads();

    // ---------------- conv1 (3x3x1x16) + relu + 2x2 maxpool ------------------------
    // writes BOTH the aligned row s_p1 and the 1-shifted row s_p1s.
    // 768 half-row units (im, co, py, half).
    for (int u = tid; u < 768; u += 320) {
        const int im   = u / 384;
        const int rem  = u - im * 384;
        const int half = rem & 1;
        const int idx  = rem >> 1;
        const int co   = idx & 15;
        const int py   = idx >> 4;          // 0..11
        float w[9];
        #pragma unroll
        for (int k = 0; k < 9; k++) w[k] = s_w1[k * 16 + co];
        const float bias = s_b1[co];
        const float* in0 = s_img + im * 784 + (2 * py) * 28;
        const int rowoff = im * 2304 + (co * 12 + py) * 12;
        float* p1row  = s_p1  + rowoff;
        float* p1srow = s_p1s + rowoff;
        const int px0 = half * 6;

        float win[4][4];
        #pragma unroll
        for (int r = 0; r < 4; r++) {
            const float2 v = *(const float2*)(in0 + r * 28 + 2 * px0);
            win[r][2] = v.x; win[r][3] = v.y;
        }
        #pragma unroll
        for (int dpx = 0; dpx < 6; dpx++) {
            const int px = px0 + dpx;
            #pragma unroll
            for (int r = 0; r < 4; r++) {
                win[r][0] = win[r][2];
                win[r][1] = win[r][3];
                const float2 v = *(const float2*)(in0 + r * 28 + 2 * px + 2);
                win[r][2] = v.x; win[r][3] = v.y;
            }
            float best = -1e30f;
            #pragma unroll
            for (int dy = 0; dy < 2; dy++) {
                #pragma unroll
                for (int dx = 0; dx < 2; dx++) {
                    float acc = bias;
                    #pragma unroll
                    for (int ky = 0; ky < 3; ky++) {
                        #pragma unroll
                        for (int kx = 0; kx < 3; kx++)
                            acc += win[dy + ky][dx + kx] * w[ky * 3 + kx];
                    }
                    best = fmaxf(best, acc);
                }
            }
            const float v = fmaxf(best, 0.0f);
            p1row[px] = v;
            if (px > 0) p1srow[px - 1] = v;   // shifted copy: s[i] = a[i+1]
        }
    }
    __syncthreads();

    // ---------------- conv2 (3x3x16x32) + relu + FUSED 2x2 maxpool, FMA2 -----------
    // thread = (im, co, oyp): 2 x 32 x 5 = 320 units. Packed pairs throughout:
    //   acc0[c]/acc1[c] hold output columns (2c, 2c+1) for output rows 0/1.
    //   tap0 pair = aligned pair c; tap1 = shifted pair c; tap2 = aligned pair c+1.
    {
        const int im  = tid >= 160;
        const int t   = tid - im * 160;    // mod-160 (not a pow2 mask!)
        const int co  = t & 31;
        const int oyp = t >> 5;            // 0..4
        const float bias = s_b2[co];
        u64 bias2; PACK2(bias2, bias, bias);
        u64 acc0[5], acc1[5];
        #pragma unroll
        for (int c = 0; c < 5; c++) { acc0[c] = bias2; acc1[c] = bias2; }

        const int ibase = im * 2304;

        #pragma unroll 1
        for (int ci = 0; ci < 16; ci++) {
            const u64* wb = s_w2d + ci * 32 + co;   // lanes=co: consecutive u64
            u64 w[9];
            #pragma unroll
            for (int k = 0; k < 9; k++) w[k] = wb[k * 512];

            const int rbase = ibase + (ci * 12 + 2 * oyp) * 12;
            #pragma unroll
            for (int r = 0; r < 4; r++) {
                const ulonglong2* pa = (const ulonglong2*)(s_p1  + rbase + r * 12);
                const ulonglong2* ps = (const ulonglong2*)(s_p1s + rbase + r * 12);
                const ulonglong2 A0 = pa[0], A1 = pa[1], A2 = pa[2];
                const ulonglong2 S0 = ps[0], S1 = ps[1], S2 = ps[2];
                const u64 al[6] = {A0.x, A0.y, A1.x, A1.y, A2.x, A2.y};
                const u64 sh[5] = {S0.x, S0.y, S1.x, S1.y, S2.x};
                if (r < 3) {               // row r = tap-row r for output row 0
                    const u64 t0 = w[r * 3], t1 = w[r * 3 + 1], t2 = w[r * 3 + 2];
                    #pragma unroll
                    for (int c = 0; c < 5; c++) {
                        FMA2(acc0[c], al[c], t0);
                        FMA2(acc0[c], sh[c], t1);
                        FMA2(acc0[c], al[c + 1], t2);
                    }
                }
                if (r >= 1) {              // row r = tap-row r-1 for output row 1
                    const u64 t0 = w[(r - 1) * 3], t1 = w[(r - 1) * 3 + 1],
                              t2 = w[(r - 1) * 3 + 2];
                    #pragma unroll
                    for (int c = 0; c < 5; c++) {
                        FMA2(acc1[c], al[c], t0);
                        FMA2(acc1[c], sh[c], t1);
                        FMA2(acc1[c], al[c + 1], t2);
                    }
                }
            }
        }
        // fused relu + 2x2 pool: pooling pairs live inside each u64
        float* dst = s_p2 + im * 800 + (oyp * 5) * 32 + co;
        #pragma unroll
        for (int c = 0; c < 5; c++) {
            float l0, h0, l1, h1;
            UNPACK2(l0, h0, acc0[c]);
            UNPACK2(l1, h1, acc1[c]);
            const float m = fmaxf(fmaxf(l0, h0), fmaxf(l1, h1));
            dst[c * 32] = fmaxf(m, 0.0f);
        }
    }
    __syncthreads();

    // ---------------- dense 800 -> 4, both images ----------------------------------
    {
        float pA0 = 0.f, pA1 = 0.f, pA2 = 0.f, pA3 = 0.f;
        float pB0 = 0.f, pB1 = 0.f, pB2 = 0.f, pB3 = 0.f;
        for (int k = tid; k < 800; k += 320) {
            const float vA = s_p2[k];
            const float vB = s_p2[800 + k];
            const float4 w = *(const float4*)(dwg + k * 4);
            pA0 += vA * w.x; pA1 += vA * w.y; pA2 += vA * w.z; pA3 += vA * w.w;
            pB0 += vB * w.x; pB1 += vB * w.y; pB2 += vB * w.z; pB3 += vB * w.w;
        }
        #pragma unroll
        for (int off = 16; off; off >>= 1) {
            pA0 += __shfl_down_sync(0xffffffffu, pA0, off);
            pA1 += __shfl_down_sync(0xffffffffu, pA1, off);
            pA2 += __shfl_down_sync(0xffffffffu, pA2, off);
            pA3 += __shfl_down_sync(0xffffffffu, pA3, off);
            pB0 += __shfl_down_sync(0xffffffffu, pB0, off);
            pB1 += __shfl_down_sync(0xffffffffu, pB1, off);
            pB2 += __shfl_down_sync(0xffffffffu, pB2, off);
            pB3 += __shfl_down_sync(0xffffffffu, pB3, off);
        }
        if ((tid & 31) == 0) {
            atomicAdd(&s_feat[0], pA0);
            atomicAdd(&s_feat[1], pA1);
            atomicAdd(&s_feat[2], pA2);
            atomicAdd(&s_feat[3], pA3);
            atomicAdd(&s_feat[4], pB0);
            atomicAdd(&s_feat[5], pB1);
            atomicAdd(&s_feat[6], pB2);
            atomicAdd(&s_feat[7], pB3);
        }
    }
    __syncthreads();

    // ---------------- analytic quantum circuit + sigmoid ---------------------------
    if (tid < 8) {
        const int im = tid >> 2;
        const int j  = tid & 3;
        if (im == 0 || has2) {
            float pr1[4];
            #pragma unroll
            for (int i = 0; i < 4; i++) {
                const float f = tanhf(s_feat[im * 4 + i]);
                pr1[i] = 0.5f * (1.0f + sinf(f));
            }
            float wj[4];
            #pragma unroll
            for (int i = 0; i < 4; i++) wj[i] = qwg[i * 4 + j];

            float q = 0.0f;
            #pragma unroll
            for (int b = 0; b < 16; b++) {
                float prob = 1.0f, ang = 0.0f;
                #pragma unroll
                for (int i = 0; i < 4; i++) {
                    if (b & (1 << i)) { prob *= pr1[i];        ang += wj[i]; }
                    else              { prob *= 1.0f - pr1[i]; }
                }
                q -= prob * sinf(ang);
            }
            out[(img0 + im) * 4 + j] = 1.0f / (1.0f + expf(-10.0f * q));
        }
    }
}

extern "C" void kernel_launch(void* const* d_in, const int* in_sizes, int n_in,
                              void* d_out, int out_size)
{
    const float* x   = (const float*)d_in[0];
    const float* w1  = (const float*)d_in[1];
    const float* b1  = (const float*)d_in[2];
    const float* w2  = (const float*)d_in[3];
    const float* b2  = (const float*)d_in[4];
    const float* dw  = (const float*)d_in[5];
    const float* db  = (const float*)d_in[6];
    const float* qw  = (const float*)d_in[7];
    float* out = (float*)d_out;

    const int B = in_sizes[0] / 784;   // NHWC 28*28*1
    static bool attr_set = false;
    if (!attr_set) {
        cudaFuncSetAttribute(hybrid_kernel,
                             cudaFuncAttributeMaxDynamicSharedMemorySize, SM_BYTES);
        attr_set = true;
    }
    hybrid_kernel<<<(B + 1) / 2, 320, SM_BYTES>>>(x, w1, b1, w2, b2, dw, db, qw, out, B);
}

// round 12
// speedup vs baseline: 1.6300x; 1.6300x over previous
#include <cuda_runtime.h>
#include <cuda_fp16.h>
#include <math.h>

// Fused CNN + analytic quantum circuit. One CTA per TWO images, 416 threads
// (13 warps). conv2 runs on TENSOR CORES: 9 tap-GEMMs C[200x32] += A_k * W_k
// via mma.sync.m16n8k16 with fp16 hi/lo split (3 MMAs) for fp32-level accuracy.
// Activations live in smem as [im][y][x][ci] so each tap's A matrix is a strided
// view (ldmatrix rowbase + tap offset) -- no im2col materialization.
//
// Quantum part collapses analytically:
//   P_i(1) = (1 + sin f_i)/2
//   <Z_j>  = - sum_{b in {0,1}^4} prod_i P_i(b_i) * sin( sum_{i: b_i=1} w[i][j] )
//   out_j  = sigmoid(10 * <Z_j>)

#define LDSM4(r0, r1, r2, r3, addr) \
    asm volatile("ldmatrix.sync.aligned.m8n8.x4.shared.b16 {%0,%1,%2,%3}, [%4];" \
        : "=r"(r0), "=r"(r1), "=r"(r2), "=r"(r3) : "r"(addr))

#define MMA16816(c, a0, a1, a2, a3, b0, b1) \
    asm volatile("mma.sync.aligned.m16n8k16.row.col.f32.f16.f16.f32 " \
        "{%0,%1,%2,%3}, {%4,%5,%6,%7}, {%8,%9}, {%0,%1,%2,%3};" \
        : "+f"(c[0]), "+f"(c[1]), "+f"(c[2]), "+f"(c[3]) \
        : "r"(a0), "r"(a1), "r"(a2), "r"(a3), "r"(b0), "r"(b1))

__device__ __forceinline__ unsigned pack_h2(__half a, __half b) {
    return (unsigned)__half_as_ushort(a) | ((unsigned)__half_as_ushort(b) << 16);
}

// shared-memory layout (float units); all blocks 16B-aligned
#define OFF_IMG    0        // [1600] phase A: 2 images; phase E: s_p2 [2][800]
#define OFF_C      1600     // [6656] conv2 output C[208][32] f32
#define OFF_ACT_HI 8256     // half[6912] = [3 imgs][12][12][16] (img2 zeroed pad)
#define OFF_ACT_LO 11712    // half[6912]
#define OFF_BF_HI  15168    // u32[2304] B fragments hi: [tap][nt][lane][w]
#define OFF_BF_LO  17472    // u32[2304]
#define OFF_W1     19776    // [144]
#define OFF_B1     19920    // [16]
#define OFF_B2     19936    // [32]
#define OFF_FEAT   19968    // [8]
#define SM_FLOATS  19976
#define SM_BYTES   (SM_FLOATS * 4)

#define NT 416              // 13 warps

__global__ __launch_bounds__(NT, 2)
void hybrid_kernel(const float* __restrict__ x,
                   const float* __restrict__ w1g, const float* __restrict__ b1g,
                   const float* __restrict__ w2g, const float* __restrict__ b2g,
                   const float* __restrict__ dwg, const float* __restrict__ dbg,
                   const float* __restrict__ qwg,
                   float* __restrict__ out, int B)
{
    extern __shared__ __align__(16) float sm[];
    float*    s_img    = sm + OFF_IMG;   // phase A
    float*    s_p2     = sm + OFF_IMG;   // phase E (images dead after conv1)
    float*    s_C      = sm + OFF_C;
    __half*   s_act_hi = (__half*)(sm + OFF_ACT_HI);
    __half*   s_act_lo = (__half*)(sm + OFF_ACT_LO);
    unsigned* s_bf_hi  = (unsigned*)(sm + OFF_BF_HI);
    unsigned* s_bf_lo  = (unsigned*)(sm + OFF_BF_LO);
    float*    s_w1     = sm + OFF_W1;
    float*    s_b1     = sm + OFF_B1;
    float*    s_b2     = sm + OFF_B2;
    float*    s_feat   = sm + OFF_FEAT;

    const int tid  = threadIdx.x;
    const int img0 = blockIdx.x * 2;
    const bool has2 = (img0 + 1) < B;
    const int nimg = has2 ? 2 : 1;

    // ---------------- load phase ----------------
    {
        const float* xin = x + img0 * 784;
        const int cnt = nimg * 784;
        for (int i = tid; i < cnt; i += NT) s_img[i] = xin[i];
    }
    // build conv2 weight fragments (hi/lo) directly in mma B-fragment layout:
    // word w of lane l, ntile nt, tap: halves (k,n),(k+1,n) with
    // k=(l&3)*2+8w, n=nt*8+l/4.  idx = tap*256 + nt*64 + l*2 + w.
    for (int idx = tid; idx < 2304; idx += NT) {
        const int w    = idx & 1;
        const int ln   = (idx >> 1) & 31;
        const int nt   = (idx >> 6) & 3;
        const int tap  = idx >> 8;
        const int k    = (ln & 3) * 2 + 8 * w;
        const int n    = nt * 8 + (ln >> 2);
        const float v0 = w2g[tap * 512 + k * 32 + n];
        const float v1 = w2g[tap * 512 + (k + 1) * 32 + n];
        const __half h0 = __float2half_rn(v0), h1 = __float2half_rn(v1);
        const __half l0 = __float2half_rn(v0 - __half2float(h0));
        const __half l1 = __float2half_rn(v1 - __half2float(h1));
        s_bf_hi[idx] = pack_h2(h0, h1);
        s_bf_lo[idx] = pack_h2(l0, l1);
    }
    // zero the pad-image activation region (rows for positions >= 200)
    {
        unsigned* zh = (unsigned*)(s_act_hi + 4608);
        unsigned* zl = (unsigned*)(s_act_lo + 4608);
        for (int i = tid; i < 1152; i += NT) { zh[i] = 0u; zl[i] = 0u; }
    }
    for (int i = tid; i < 144; i += NT) s_w1[i] = w1g[i];
    if (tid < 16) s_b1[tid] = b1g[tid];
    if (tid < 32) s_b2[tid] = b2g[tid];
    if (tid < 8)  s_feat[tid] = dbg[tid & 3];
    __syncthreads();

    // ---------------- conv1 (3x3x1x16) + relu + 2x2 maxpool -> s_act hi/lo ---------
    // 768 half-row units (im, ci, py, half); output layout [im][py][px][ci] fp16.
    for (int u = tid; u < 768; u += NT) {
        const int im   = u / 384;
        const int rem  = u - im * 384;
        const int half = rem & 1;
        const int idx  = rem >> 1;
        const int co   = idx & 15;          // conv1 out channel = conv2 ci
        const int py   = idx >> 4;          // 0..11
        float w[9];
        #pragma unroll
        for (int k = 0; k < 9; k++) w[k] = s_w1[k * 16 + co];
        const float bias = s_b1[co];
        const float* in0 = s_img + im * 784 + (2 * py) * 28;
        const int px0 = half * 6;

        float win[4][4];
        #pragma unroll
        for (int r = 0; r < 4; r++) {
            const float2 v = *(const float2*)(in0 + r * 28 + 2 * px0);
            win[r][2] = v.x; win[r][3] = v.y;
        }
        #pragma unroll
        for (int dpx = 0; dpx < 6; dpx++) {
            const int px = px0 + dpx;
            #pragma unroll
            for (int r = 0; r < 4; r++) {
                win[r][0] = win[r][2];
                win[r][1] = win[r][3];
                const float2 v = *(const float2*)(in0 + r * 28 + 2 * px + 2);
                win[r][2] = v.x; win[r][3] = v.y;
            }
            float best = -1e30f;
            #pragma unroll
            for (int dy = 0; dy < 2; dy++) {
                #pragma unroll
                for (int dx = 0; dx < 2; dx++) {
                    float acc = bias;
                    #pragma unroll
                    for (int ky = 0; ky < 3; ky++) {
                        #pragma unroll
                        for (int kx = 0; kx < 3; kx++)
                            acc += win[dy + ky][dx + kx] * w[ky * 3 + kx];
                    }
                    best = fmaxf(best, acc);
                }
            }
            const float v = fmaxf(best, 0.0f);
            const __half h = __float2half_rn(v);
            const __half l = __float2half_rn(v - __half2float(h));
            const int ei = im * 2304 + (py * 12 + px) * 16 + co;
            s_act_hi[ei] = h;
            s_act_lo[ei] = l;
        }
    }
    __syncthreads();

    // ---------------- conv2 on tensor cores: C[208][32] = sum_tap A_tap * W_tap ----
    // warp = m-tile (16 positions). Position p = im*100 + oy*10 + ox; p>=200 pads
    // point at the zeroed image-2 region.
    {
        const int wid  = tid >> 5;
        const int lane = tid & 31;
        const int m    = lane & 15;
        const int p    = wid * 16 + m;
        int row_elems;
        if (p < 200) {
            const int imq = p / 100;
            const int rq  = p - imq * 100;
            row_elems = imq * 2304 + (rq / 10) * 192 + (rq % 10) * 16;
        } else {
            row_elems = 4608;      // zeroed pad region
        }
        const int koff = (lane >> 4) * 8;
        const unsigned ah_base = (unsigned)__cvta_generic_to_shared(s_act_hi)
                                 + (unsigned)(row_elems + koff) * 2u;
        const unsigned al_base = (unsigned)__cvta_generic_to_shared(s_act_lo)
                                 + (unsigned)(row_elems + koff) * 2u;

        float acc[4][4];
        #pragma unroll
        for (int nt = 0; nt < 4; nt++)
            #pragma unroll
            for (int c = 0; c < 4; c++) acc[nt][c] = 0.0f;

        #pragma unroll
        for (int tap = 0; tap < 9; tap++) {
            const unsigned toff = (unsigned)(((tap / 3) * 12 + (tap % 3)) * 32);
            unsigned ah0, ah1, ah2, ah3, al0, al1, al2, al3;
            LDSM4(ah0, ah1, ah2, ah3, ah_base + toff);
            LDSM4(al0, al1, al2, al3, al_base + toff);
            #pragma unroll
            for (int nt = 0; nt < 4; nt++) {
                const uint2 bh = *(const uint2*)(s_bf_hi + (tap * 4 + nt) * 64 + lane * 2);
                const uint2 bl = *(const uint2*)(s_bf_lo + (tap * 4 + nt) * 64 + lane * 2);
                MMA16816(acc[nt], ah0, ah1, ah2, ah3, bh.x, bh.y);
                MMA16816(acc[nt], al0, al1, al2, al3, bh.x, bh.y);
                MMA16816(acc[nt], ah0, ah1, ah2, ah3, bl.x, bl.y);
            }
        }
        // epilogue: fragment -> s_C[p][co]
        const int prow = wid * 16 + (lane >> 2);
        const int col0 = (lane & 3) * 2;
        #pragma unroll
        for (int nt = 0; nt < 4; nt++) {
            const int co0 = nt * 8 + col0;
            *(float2*)&s_C[prow * 32 + co0]       = make_float2(acc[nt][0], acc[nt][1]);
            *(float2*)&s_C[(prow + 8) * 32 + co0] = make_float2(acc[nt][2], acc[nt][3]);
        }
    }
    __syncthreads();

    // ---------------- bias + relu + 2x2 maxpool -> s_p2[2][800] --------------------
    // (max commutes with +bias; relu applied after)
    for (int o = tid; o < 1600; o += NT) {
        const int im  = o >= 800;
        const int oo  = o - im * 800;
        const int co  = oo & 31;
        const int pos = oo >> 5;
        const int r   = pos / 5;
        const int cl  = pos - r * 5;
        const int pb  = im * 100 + (2 * r) * 10 + 2 * cl;
        const float v0 = s_C[(pb     ) * 32 + co];
        const float v1 = s_C[(pb +  1) * 32 + co];
        const float v2 = s_C[(pb + 10) * 32 + co];
        const float v3 = s_C[(pb + 11) * 32 + co];
        const float mx = fmaxf(fmaxf(v0, v1), fmaxf(v2, v3)) + s_b2[co];
        s_p2[o] = fmaxf(mx, 0.0f);
    }
    __syncthreads();

    // ---------------- dense 800 -> 4, both images ----------------------------------
    {
        float pA0 = 0.f, pA1 = 0.f, pA2 = 0.f, pA3 = 0.f;
        float pB0 = 0.f, pB1 = 0.f, pB2 = 0.f, pB3 = 0.f;
        for (int k = tid; k < 800; k += NT) {
            const float vA = s_p2[k];
            const float vB = s_p2[800 + k];
            const float4 w = *(const float4*)(dwg + k * 4);
            pA0 += vA * w.x; pA1 += vA * w.y; pA2 += vA * w.z; pA3 += vA * w.w;
            pB0 += vB * w.x; pB1 += vB * w.y; pB2 += vB * w.z; pB3 += vB * w.w;
        }
        #pragma unroll
        for (int off = 16; off; off >>= 1) {
            pA0 += __shfl_down_sync(0xffffffffu, pA0, off);
            pA1 += __shfl_down_sync(0xffffffffu, pA1, off);
            pA2 += __shfl_down_sync(0xffffffffu, pA2, off);
            pA3 += __shfl_down_sync(0xffffffffu, pA3, off);
            pB0 += __shfl_down_sync(0xffffffffu, pB0, off);
            pB1 += __shfl_down_sync(0xffffffffu, pB1, off);
            pB2 += __shfl_down_sync(0xffffffffu, pB2, off);
            pB3 += __shfl_down_sync(0xffffffffu, pB3, off);
        }
        if ((tid & 31) == 0) {
            atomicAdd(&s_feat[0], pA0);
            atomicAdd(&s_feat[1], pA1);
            atomicAdd(&s_feat[2], pA2);
            atomicAdd(&s_feat[3], pA3);
            atomicAdd(&s_feat[4], pB0);
            atomicAdd(&s_feat[5], pB1);
            atomicAdd(&s_feat[6], pB2);
            atomicAdd(&s_feat[7], pB3);
        }
    }
    __syncthreads();

    // ---------------- analytic quantum circuit + sigmoid ---------------------------
    if (tid < 8) {
        const int im = tid >> 2;
        const int j  = tid & 3;
        if (im == 0 || has2) {
            float pr1[4];
            #pragma unroll
            for (int i = 0; i < 4; i++) {
                const float f = tanhf(s_feat[im * 4 + i]);
                pr1[i] = 0.5f * (1.0f + sinf(f));
            }
            float wj[4];
            #pragma unroll
            for (int i = 0; i < 4; i++) wj[i] = qwg[i * 4 + j];

            float q = 0.0f;
            #pragma unroll
            for (int b = 0; b < 16; b++) {
                float prob = 1.0f, ang = 0.0f;
                #pragma unroll
                for (int i = 0; i < 4; i++) {
                    if (b & (1 << i)) { prob *= pr1[i];        ang += wj[i]; }
                    else              { prob *= 1.0f - pr1[i]; }
                }
                q -= prob * sinf(ang);
            }
            out[(img0 + im) * 4 + j] = 1.0f / (1.0f + expf(-10.0f * q));
        }
    }
}

extern "C" void kernel_launch(void* const* d_in, const int* in_sizes, int n_in,
                              void* d_out, int out_size)
{
    const float* x   = (const float*)d_in[0];
    const float* w1  = (const float*)d_in[1];
    const float* b1  = (const float*)d_in[2];
    const float* w2  = (const float*)d_in[3];
    const float* b2  = (const float*)d_in[4];
    const float* dw  = (const float*)d_in[5];
    const float* db  = (const float*)d_in[6];
    const float* qw  = (const float*)d_in[7];
    float* out = (float*)d_out;

    const int B = in_sizes[0] / 784;   // NHWC 28*28*1
    static bool attr_set = false;
    if (!attr_set) {
        cudaFuncSetAttribute(hybrid_kernel,
                             cudaFuncAttributeMaxDynamicSharedMemorySize, SM_BYTES);
        attr_set = true;
    }
    hybrid_kernel<<<(B + 1) / 2, NT, SM_BYTES>>>(x, w1, b1, w2, b2, dw, db, qw, out, B);
}

// round 13
// speedup vs baseline: 1.9341x; 1.1866x over previous
#include <cuda_runtime.h>
#include <cuda_fp16.h>
#include <math.h>

// Fused CNN + analytic quantum circuit. One CTA per FOUR images, 416 threads
// (13 warps). conv2 on TENSOR CORES: 9 tap-GEMMs C[400x32] += A_k * W_k via
// mma.sync.m16n8k16, fp16 hi/lo split (3 MMAs) for fp32-level accuracy.
// Each warp computes 2 m-tiles, reusing B fragments from registers.
// C aliases the (dead-after-MMA) activation+fragment region.
//
// Quantum part collapses analytically:
//   P_i(1) = (1 + sin f_i)/2
//   <Z_j>  = - sum_{b in {0,1}^4} prod_i P_i(b_i) * sin( sum_{i: b_i=1} w[i][j] )
//   out_j  = sigmoid(10 * <Z_j>)

#define LDSM4(r0, r1, r2, r3, addr) \
    asm volatile("ldmatrix.sync.aligned.m8n8.x4.shared.b16 {%0,%1,%2,%3}, [%4];" \
        : "=r"(r0), "=r"(r1), "=r"(r2), "=r"(r3) : "r"(addr))

#define MMA16816(c, a0, a1, a2, a3, b0, b1) \
    asm volatile("mma.sync.aligned.m16n8k16.row.col.f32.f16.f16.f32 " \
        "{%0,%1,%2,%3}, {%4,%5,%6,%7}, {%8,%9}, {%0,%1,%2,%3};" \
        : "+f"(c[0]), "+f"(c[1]), "+f"(c[2]), "+f"(c[3]) \
        : "r"(a0), "r"(a1), "r"(a2), "r"(a3), "r"(b0), "r"(b1))

__device__ __forceinline__ unsigned pack_h2(__half a, __half b) {
    return (unsigned)__half_as_ushort(a) | ((unsigned)__half_as_ushort(b) << 16);
}

// shared-memory layout (float units); all blocks 16B-aligned
// UNION region (floats 3200..17792) holds act_hi/act_lo/bf during MMA,
// then C[416][32] f32 after the post-MMA barrier.
#define OFF_IMG    0        // [3200] phase A: 4 images [3136]; phase E: s_p2 [4][800]
#define OFF_ACT_HI 3200     // half[9984] = [4][12][12][16] + 768 zero-pad
#define OFF_ACT_LO 8192     // half[9984]
#define OFF_BF_HI  13184    // u32[2304] B fragments hi: [tap][nt][lane][w]
#define OFF_BF_LO  15488    // u32[2304]
#define OFF_C      3200     // [13312] C[416][32] f32 (aliases act+bf, post-barrier)
#define OFF_W1     17792    // [144]
#define OFF_B1     17936    // [16]
#define OFF_B2     17952    // [32]
#define OFF_FEAT   17984    // [16]
#define SM_FLOATS  18000
#define SM_BYTES   (SM_FLOATS * 4)

#define NT 416              // 13 warps

__global__ __launch_bounds__(NT, 2)
void hybrid_kernel(const float* __restrict__ x,
                   const float* __restrict__ w1g, const float* __restrict__ b1g,
                   const float* __restrict__ w2g, const float* __restrict__ b2g,
                   const float* __restrict__ dwg, const float* __restrict__ dbg,
                   const float* __restrict__ qwg,
                   float* __restrict__ out, int B)
{
    extern __shared__ __align__(16) float sm[];
    float*    s_img    = sm + OFF_IMG;   // phase A
    float*    s_p2     = sm + OFF_IMG;   // phase E (images dead after conv1)
    float*    s_C      = sm + OFF_C;     // post-MMA (act/bf dead)
    __half*   s_act_hi = (__half*)(sm + OFF_ACT_HI);
    __half*   s_act_lo = (__half*)(sm + OFF_ACT_LO);
    unsigned* s_bf_hi  = (unsigned*)(sm + OFF_BF_HI);
    unsigned* s_bf_lo  = (unsigned*)(sm + OFF_BF_LO);
    float*    s_w1     = sm + OFF_W1;
    float*    s_b1     = sm + OFF_B1;
    float*    s_b2     = sm + OFF_B2;
    float*    s_feat   = sm + OFF_FEAT;

    const int tid  = threadIdx.x;
    const int img0 = blockIdx.x * 4;
    const int nimg = min(4, B - img0);

    // ---------------- load phase ----------------
    {
        const float* xin = x + img0 * 784;
        const int cnt = nimg * 784;
        for (int i = tid; i < cnt; i += NT) s_img[i] = xin[i];
    }
    // conv2 weight fragments (hi/lo) in mma B-fragment layout:
    // word w of lane l, ntile nt, tap: halves (k,n),(k+1,n), k=(l&3)*2+8w, n=nt*8+l/4
    for (int idx = tid; idx < 2304; idx += NT) {
        const int w    = idx & 1;
        const int ln   = (idx >> 1) & 31;
        const int nt   = (idx >> 6) & 3;
        const int tap  = idx >> 8;
        const int k    = (ln & 3) * 2 + 8 * w;
        const int n    = nt * 8 + (ln >> 2);
        const float v0 = w2g[tap * 512 + k * 32 + n];
        const float v1 = w2g[tap * 512 + (k + 1) * 32 + n];
        const __half h0 = __float2half_rn(v0), h1 = __float2half_rn(v1);
        const __half l0 = __float2half_rn(v0 - __half2float(h0));
        const __half l1 = __float2half_rn(v1 - __half2float(h1));
        s_bf_hi[idx] = pack_h2(h0, h1);
        s_bf_lo[idx] = pack_h2(l0, l1);
    }
    // zero the pad rows (positions >= 400) + ldsm/tap reach: 768 halves each
    {
        unsigned* zh = (unsigned*)(s_act_hi + 9216);
        unsigned* zl = (unsigned*)(s_act_lo + 9216);
        for (int i = tid; i < 384; i += NT) { zh[i] = 0u; zl[i] = 0u; }
    }
    for (int i = tid; i < 144; i += NT) s_w1[i] = w1g[i];
    if (tid < 16) s_b1[tid] = b1g[tid];
    if (tid < 32) s_b2[tid] = b2g[tid];
    if (tid < 16) s_feat[tid] = dbg[tid & 3];
    __syncthreads();

    // ---------------- conv1 (3x3x1x16) + relu + 2x2 maxpool -> s_act hi/lo ---------
    // up to 1536 half-row units (im, ci, py, half); layout [im][py][px][16] fp16.
    for (int u = tid; u < nimg * 384; u += NT) {
        const int im   = u / 384;
        const int rem  = u - im * 384;
        const int half = rem & 1;
        const int idx  = rem >> 1;
        const int co   = idx & 15;
        const int py   = idx >> 4;          // 0..11
        float w[9];
        #pragma unroll
        for (int k = 0; k < 9; k++) w[k] = s_w1[k * 16 + co];
        const float bias = s_b1[co];
        const float* in0 = s_img + im * 784 + (2 * py) * 28;
        const int px0 = half * 6;

        float win[4][4];
        #pragma unroll
        for (int r = 0; r < 4; r++) {
            const float2 v = *(const float2*)(in0 + r * 28 + 2 * px0);
            win[r][2] = v.x; win[r][3] = v.y;
        }
        #pragma unroll
        for (int dpx = 0; dpx < 6; dpx++) {
            const int px = px0 + dpx;
            #pragma unroll
            for (int r = 0; r < 4; r++) {
                win[r][0] = win[r][2];
                win[r][1] = win[r][3];
                const float2 v = *(const float2*)(in0 + r * 28 + 2 * px + 2);
                win[r][2] = v.x; win[r][3] = v.y;
            }
            float best = -1e30f;
            #pragma unroll
            for (int dy = 0; dy < 2; dy++) {
                #pragma unroll
                for (int dx = 0; dx < 2; dx++) {
                    float acc = bias;
                    #pragma unroll
                    for (int ky = 0; ky < 3; ky++) {
                        #pragma unroll
                        for (int kx = 0; kx < 3; kx++)
                            acc += win[dy + ky][dx + kx] * w[ky * 3 + kx];
                    }
                    best = fmaxf(best, acc);
                }
            }
            const float v = fmaxf(best, 0.0f);
            const __half h = __float2half_rn(v);
            const __half l = __float2half_rn(v - __half2float(h));
            const int ei = im * 2304 + (py * 12 + px) * 16 + co;
            s_act_hi[ei] = h;
            s_act_lo[ei] = l;
        }
    }
    __syncthreads();

    // ---------------- conv2 on tensor cores: C[416][32] = sum_tap A_tap * W_tap ----
    // warp owns m-tiles {wid, wid+13}; B fragments loaded once, used for both.
    {
        const int wid  = tid >> 5;
        const int lane = tid & 31;
        const int m    = lane & 15;
        const int koff = (lane >> 4) * 8;
        const unsigned hi_base = (unsigned)__cvta_generic_to_shared(s_act_hi);
        const unsigned lo_base = (unsigned)__cvta_generic_to_shared(s_act_lo);

        unsigned ahb[2], alb[2];
        #pragma unroll
        for (int t = 0; t < 2; t++) {
            const int p = (wid + t * 13) * 16 + m;
            int row_elems;
            if (p < 400) {
                const int imq = p / 100;
                const int rq  = p - imq * 100;
                row_elems = imq * 2304 + (rq / 10) * 192 + (rq % 10) * 16;
            } else {
                row_elems = 9216 + (p - 400) * 16;   // zeroed pad
            }
            ahb[t] = hi_base + (unsigned)(row_elems + koff) * 2u;
            alb[t] = lo_base + (unsigned)(row_elems + koff) * 2u;
        }

        float acc[2][4][4];
        #pragma unroll
        for (int t = 0; t < 2; t++)
            #pragma unroll
            for (int nt = 0; nt < 4; nt++)
                #pragma unroll
                for (int c = 0; c < 4; c++) acc[t][nt][c] = 0.0f;

        #pragma unroll
        for (int tap = 0; tap < 9; tap++) {
            const unsigned toff = (unsigned)(((tap / 3) * 12 + (tap % 3)) * 32);
            unsigned ah[2][4], al[2][4];
            #pragma unroll
            for (int t = 0; t < 2; t++) {
                LDSM4(ah[t][0], ah[t][1], ah[t][2], ah[t][3], ahb[t] + toff);
                LDSM4(al[t][0], al[t][1], al[t][2], al[t][3], alb[t] + toff);
            }
            #pragma unroll
            for (int nt = 0; nt < 4; nt++) {
                const uint2 bh = *(const uint2*)(s_bf_hi + (tap * 4 + nt) * 64 + lane * 2);
                const uint2 bl = *(const uint2*)(s_bf_lo + (tap * 4 + nt) * 64 + lane * 2);
                #pragma unroll
                for (int t = 0; t < 2; t++) {
                    MMA16816(acc[t][nt], ah[t][0], ah[t][1], ah[t][2], ah[t][3], bh.x, bh.y);
                    MMA16816(acc[t][nt], al[t][0], al[t][1], al[t][2], al[t][3], bh.x, bh.y);
                    MMA16816(acc[t][nt], ah[t][0], ah[t][1], ah[t][2], ah[t][3], bl.x, bl.y);
                }
            }
        }
        __syncthreads();   // all act/bf reads done -> C may overwrite them

        // epilogue: fragments -> s_C[p][co]
        const int col0 = (lane & 3) * 2;
        #pragma unroll
        for (int t = 0; t < 2; t++) {
            const int prow = (wid + t * 13) * 16 + (lane >> 2);
            #pragma unroll
            for (int nt = 0; nt < 4; nt++) {
                const int co0 = nt * 8 + col0;
                *(float2*)&s_C[prow * 32 + co0]       = make_float2(acc[t][nt][0], acc[t][nt][1]);
                *(float2*)&s_C[(prow + 8) * 32 + co0] = make_float2(acc[t][nt][2], acc[t][nt][3]);
            }
        }
    }
    __syncthreads();

    // ---------------- bias + relu + 2x2 maxpool -> s_p2[4][800] --------------------
    for (int o = tid; o < nimg * 800; o += NT) {
        const int im  = o / 800;
        const int oo  = o - im * 800;
        const int co  = oo & 31;
        const int pos = oo >> 5;
        const int r   = pos / 5;
        const int cl  = pos - r * 5;
        const int pb  = im * 100 + (2 * r) * 10 + 2 * cl;
        const float v0 = s_C[(pb     ) * 32 + co];
        const float v1 = s_C[(pb +  1) * 32 + co];
        const float v2 = s_C[(pb + 10) * 32 + co];
        const float v3 = s_C[(pb + 11) * 32 + co];
        const float mx = fmaxf(fmaxf(v0, v1), fmaxf(v2, v3)) + s_b2[co];
        s_p2[o] = fmaxf(mx, 0.0f);
    }
    __syncthreads();

    // ---------------- dense 800 -> 4, four images (one weight load serves all) -----
    {
        float p[4][4];
        #pragma unroll
        for (int g = 0; g < 4; g++)
            #pragma unroll
            for (int c = 0; c < 4; c++) p[g][c] = 0.0f;

        for (int k = tid; k < 800; k += NT) {
            const float4 w = *(const float4*)(dwg + k * 4);
            #pragma unroll
            for (int g = 0; g < 4; g++) {
                const float v = s_p2[g * 800 + k];
                p[g][0] += v * w.x; p[g][1] += v * w.y;
                p[g][2] += v * w.z; p[g][3] += v * w.w;
            }
        }
        #pragma unroll
        for (int off = 16; off; off >>= 1) {
            #pragma unroll
            for (int g = 0; g < 4; g++)
                #pragma unroll
                for (int c = 0; c < 4; c++)
                    p[g][c] += __shfl_down_sync(0xffffffffu, p[g][c], off);
        }
        if ((tid & 31) == 0) {
            #pragma unroll
            for (int g = 0; g < 4; g++)
                #pragma unroll
                for (int c = 0; c < 4; c++)
                    atomicAdd(&s_feat[g * 4 + c], p[g][c]);
        }
    }
    __syncthreads();

    // ---------------- analytic quantum circuit + sigmoid ---------------------------
    if (tid < 16) {
        const int im = tid >> 2;
        const int j  = tid & 3;
        const int img = img0 + im;
        if (img < B) {
            float pr1[4];
            #pragma unroll
            for (int i = 0; i < 4; i++) {
                const float f = tanhf(s_feat[im * 4 + i]);
                pr1[i] = 0.5f * (1.0f + sinf(f));
            }
            float wj[4];
            #pragma unroll
            for (int i = 0; i < 4; i++) wj[i] = qwg[i * 4 + j];

            float q = 0.0f;
            #pragma unroll
            for (int b = 0; b < 16; b++) {
                float prob = 1.0f, ang = 0.0f;
                #pragma unroll
                for (int i = 0; i < 4; i++) {
                    if (b & (1 << i)) { prob *= pr1[i];        ang += wj[i]; }
                    else              { prob *= 1.0f - pr1[i]; }
                }
                q -= prob * sinf(ang);
            }
            out[img * 4 + j] = 1.0f / (1.0f + expf(-10.0f * q));
        }
    }
}

extern "C" void kernel_launch(void* const* d_in, const int* in_sizes, int n_in,
                              void* d_out, int out_size)
{
    const float* x   = (const float*)d_in[0];
    const float* w1  = (const float*)d_in[1];
    const float* b1  = (const float*)d_in[2];
    const float* w2  = (const float*)d_in[3];
    const float* b2  = (const float*)d_in[4];
    const float* dw  = (const float*)d_in[5];
    const float* db  = (const float*)d_in[6];
    const float* qw  = (const float*)d_in[7];
    float* out = (float*)d_out;

    const int B = in_sizes[0] / 784;   // NHWC 28*28*1
    static bool attr_set = false;
    if (!attr_set) {
        cudaFuncSetAttribute(hybrid_kernel,
                             cudaFuncAttributeMaxDynamicSharedMemorySize, SM_BYTES);
        attr_set = true;
    }
    hybrid_kernel<<<(B + 3) / 4, NT, SM_BYTES>>>(x, w1, b1, w2, b2, dw, db, qw, out, B);
}